// round 17
// baseline (speedup 1.0000x reference)
#include <cuda_runtime.h>
#include <cuda_fp16.h>
#include <cstdint>

#define THREADS 512
#define BT      28
#define BATCH   4096
#define TT      168
#define NGRID   147

// smem byte offsets from 1024-aligned base
#define W0F    0u        // Whh0 fp16 [256][128B] SW128
#define W1HF   32768u    // Whh1
#define W1IF   65536u    // Wih1
#define W0XP   98304u    // Wih0 K-padded [256][16 fp16 = 32B] compact, 8KB
#define H0T(p)    (106496u + (p)*4096u)   // h0 tile [32][64] fp16 ping-pong
#define H1T(p)    (114688u + (p)*4096u)   // h1 tile
#define SXF(p)    (122880u + (p)*4096u)   // x fp16 tile [32 rows][128B] SW128 (cols 0-3)
#define HS_OFF    131072u                 // fp32 h1 staging [32][64]
#define SMEM_BYTES 140288

__device__ __forceinline__ uint32_t smem_u32(const void* p) {
    uint32_t a;
    asm("{ .reg .u64 t; cvta.to.shared.u64 t, %1; cvt.u32.u64 %0, t; }" : "=r"(a) : "l"(p));
    return a;
}
__device__ __forceinline__ float tanhapx(float x) {
    float y; asm("tanh.approx.f32 %0, %1;" : "=f"(y) : "f"(x)); return y;
}
__device__ __forceinline__ float fsig(float x) { return fmaf(0.5f, tanhapx(0.5f * x), 0.5f); }

__device__ __forceinline__ void ldsm4(uint32_t &r0, uint32_t &r1, uint32_t &r2, uint32_t &r3, uint32_t a) {
    asm volatile("ldmatrix.sync.aligned.m8n8.x4.shared.b16 {%0,%1,%2,%3}, [%4];"
                 : "=r"(r0), "=r"(r1), "=r"(r2), "=r"(r3) : "r"(a));
}
__device__ __forceinline__ void ldsm2(uint32_t &r0, uint32_t &r1, uint32_t a) {
    asm volatile("ldmatrix.sync.aligned.m8n8.x2.shared.b16 {%0,%1}, [%2];"
                 : "=r"(r0), "=r"(r1) : "r"(a));
}
__device__ __forceinline__ void mma_f16(float &c0, float &c1, float &c2, float &c3,
                                        uint32_t a0, uint32_t a1, uint32_t a2, uint32_t a3,
                                        uint32_t b0, uint32_t b1) {
    asm volatile("mma.sync.aligned.m16n8k16.row.col.f32.f16.f16.f32 "
                 "{%0,%1,%2,%3}, {%4,%5,%6,%7}, {%8,%9}, {%0,%1,%2,%3};"
                 : "+f"(c0), "+f"(c1), "+f"(c2), "+f"(c3)
                 : "r"(a0), "r"(a1), "r"(a2), "r"(a3), "r"(b0), "r"(b1));
}

// acc[mb][G][4] += h(A) * W(B)^T over K=64; warp covers 8 units (one n8 tile per gate)
__device__ __forceinline__ void gemm_t(float acc[2][4][4],
                                       uint32_t Ah, uint32_t Bw,
                                       const uint32_t aRow[2], const uint32_t bRow[4],
                                       uint32_t hbA, uint32_t xorA,
                                       uint32_t hbB, uint32_t xorB)
{
    #pragma unroll
    for (int kc = 0; kc < 4; kc++) {
        const uint32_t kA = ((uint32_t)(kc * 32) + hbA) ^ xorA;
        const uint32_t kB = ((uint32_t)(kc * 32) + hbB) ^ xorB;
        uint32_t a[2][4], b[4][2];
        #pragma unroll
        for (int mb = 0; mb < 2; mb++)
            ldsm4(a[mb][0], a[mb][1], a[mb][2], a[mb][3], Ah + aRow[mb] + kA);
        #pragma unroll
        for (int G = 0; G < 4; G++)
            ldsm2(b[G][0], b[G][1], Bw + bRow[G] + kB);
        #pragma unroll
        for (int mb = 0; mb < 2; mb++)
            #pragma unroll
            for (int G = 0; G < 4; G++)
                mma_f16(acc[mb][G][0], acc[mb][G][1], acc[mb][G][2], acc[mb][G][3],
                        a[mb][0], a[mb][1], a[mb][2], a[mb][3], b[G][0], b[G][1]);
    }
}

extern "C" __global__ void __launch_bounds__(THREADS, 1)
weather_lstm_ws(const float* __restrict__ x,
                const float* __restrict__ Wih0, const float* __restrict__ Whh0,
                const float* __restrict__ bih0, const float* __restrict__ bhh0,
                const float* __restrict__ Wih1, const float* __restrict__ Whh1,
                const float* __restrict__ bih1, const float* __restrict__ bhh1,
                const float* __restrict__ W1,  const float* __restrict__ b1,
                const float* __restrict__ W2,  const float* __restrict__ b2,
                float* __restrict__ out)
{
    extern __shared__ char smraw[];
    const uint32_t raw = smem_u32(smraw);
    const uint32_t BAu = (raw + 1023u) & ~1023u;
    char* BAc = smraw + (BAu - raw);

    const int t    = threadIdx.x;
    const int w    = t >> 5, lane = t & 31;
    const bool isA = (w < 8);                 // team A: layer 0 (8 warps); team B: layer 1
    const int q    = isA ? w : (w - 8);       // warp owns units 8q..8q+7 (all gates)
    const int g4   = lane >> 2, t4 = lane & 3;
    const int u0t  = 8 * q + 2 * t4;          // thread's units u0t, u0t+1
    const int bBase = blockIdx.x * BT;

    const int      rlA  = (lane & 7) + ((lane >> 3) & 1) * 8;
    const uint32_t hbA  = (uint32_t)(((lane >> 4) & 1) * 16);
    const uint32_t xorA = (uint32_t)((lane & 7) << 4);
    const int      laneB = lane & 15;
    const int      rlB  = laneB & 7;
    const uint32_t hbB  = (uint32_t)(((laneB >> 3) & 1) * 16);
    const uint32_t xorB = (uint32_t)((laneB & 7) << 4);

    uint32_t aRow[2];
    #pragma unroll
    for (int mb = 0; mb < 2; mb++) aRow[mb] = (uint32_t)((mb * 16 + rlA) * 128);
    uint32_t bRow[4];
    #pragma unroll
    for (int G = 0; G < 4; G++) bRow[G] = (uint32_t)((G * 64 + 8 * q + rlB) * 128);

    // ---- preload weights fp16 SW128 [256][64] ----
    for (int e = t; e < 256 * 64; e += THREADS) {
        int j = e >> 6, k = e & 63;
        uint32_t off = ((uint32_t)(j * 128 + k * 2)) ^ ((uint32_t)(j & 7) << 4);
        *(__half*)(BAc + W0F  + off) = __float2half_rn(Whh0[e]);
        *(__half*)(BAc + W1HF + off) = __float2half_rn(Whh1[e]);
        *(__half*)(BAc + W1IF + off) = __float2half_rn(Wih1[e]);
    }
    for (int e = t; e < 8192; e += THREADS) ((uint32_t*)(BAc + W0XP))[e] = 0u;
    __syncthreads();

    for (int e = t; e < 256 * 4; e += THREADS) {
        int j = e >> 2, i = e & 3;
        *(__half*)(BAc + W0XP + j * 32 + i * 2) = __float2half_rn(Wih0[e]);
    }
    if (t < 128) {
        int xb2 = t >> 2, xq2 = t & 3;
        float v = (bBase + xb2 < BATCH) ? x[(size_t)(bBase + xb2) * TT * 4 + xq2] : 0.f;
        uint32_t off = ((uint32_t)(xb2 * 128 + xq2 * 2)) ^ ((uint32_t)(xb2 & 7) << 4);
        *(__half*)(BAc + SXF(0) + off) = __float2half_rn(v);
    }

    float bias[4][2];
    #pragma unroll
    for (int G = 0; G < 4; G++)
        #pragma unroll
        for (int ui = 0; ui < 2; ui++) {
            int j = G * 64 + u0t + ui;
            bias[G][ui] = isA ? (bih0[j] + bhh0[j]) : (bih1[j] + bhh1[j]);
        }
    float cs[2][2][2];   // [mb][rh][ui]
    #pragma unroll
    for (int a0 = 0; a0 < 2; a0++)
        #pragma unroll
        for (int a1 = 0; a1 < 2; a1++)
            #pragma unroll
            for (int a2 = 0; a2 < 2; a2++) cs[a0][a1][a2] = 0.f;

    // x duty: team A threads 0..127 (warps 0-3)
    const int xb = t >> 2, xq = t & 3;
    const bool xduty = (t < 128);
    const bool xok   = xduty && (bBase + xb < BATCH);

    __syncthreads();

    uint32_t bwx[4][2];
    if (isA) {
        #pragma unroll
        for (int G = 0; G < 4; G++) {
            uint32_t addr = BAu + W0XP
                          + (uint32_t)((G * 64 + 8 * q + rlB) * 32)
                          + (uint32_t)(((laneB >> 3) & 1) * 16);
            ldsm2(bwx[G][0], bwx[G][1], addr);
        }
    }
    __syncthreads();

    // Wavefront: iter ts — team A computes h0[ts] (ts<TT); team B computes h1[ts-1] (ts>0).
    // All reads hit buffer p, all writes hit p^1; ONE CTA barrier per iteration.
    #pragma unroll 1
    for (int ts = 0; ts <= TT; ts++) {
        const int p = ts & 1;

        if (isA) {
            if (ts < TT) {
                float xpre = 0.f;
                if (xok && ts + 1 < TT)
                    xpre = x[((size_t)(bBase + xb) * TT + ts + 1) * 4 + xq];

                float acc[2][4][4];
                #pragma unroll
                for (int mb = 0; mb < 2; mb++)
                    #pragma unroll
                    for (int G = 0; G < 4; G++)
                        #pragma unroll
                        for (int c = 0; c < 4; c++)
                            acc[mb][G][c] = bias[G][c & 1];

                gemm_t(acc, BAu + H0T(p), BAu + W0F, aRow, bRow, hbA, xorA, hbB, xorB);
                {   // + x[ts] * Wih0^T (single K=16 chunk, resident B)
                    const uint32_t kA = hbA ^ xorA;
                    uint32_t a[2][4];
                    #pragma unroll
                    for (int mb = 0; mb < 2; mb++)
                        ldsm4(a[mb][0], a[mb][1], a[mb][2], a[mb][3],
                              BAu + SXF(p) + aRow[mb] + kA);
                    #pragma unroll
                    for (int mb = 0; mb < 2; mb++)
                        #pragma unroll
                        for (int G = 0; G < 4; G++)
                            mma_f16(acc[mb][G][0], acc[mb][G][1], acc[mb][G][2], acc[mb][G][3],
                                    a[mb][0], a[mb][1], a[mb][2], a[mb][3],
                                    bwx[G][0], bwx[G][1]);
                }

                #pragma unroll
                for (int mb = 0; mb < 2; mb++)
                    #pragma unroll
                    for (int rh = 0; rh < 2; rh++) {
                        const int b = mb * 16 + g4 + 8 * rh;
                        float hv[2];
                        #pragma unroll
                        for (int ui = 0; ui < 2; ui++) {
                            float gi = fsig   (acc[mb][0][rh * 2 + ui]);
                            float gf = fsig   (acc[mb][1][rh * 2 + ui]);
                            float gg = tanhapx(acc[mb][2][rh * 2 + ui]);
                            float go = fsig   (acc[mb][3][rh * 2 + ui]);
                            float &c = cs[mb][rh][ui];
                            c = gf * c + gi * gg;
                            hv[ui] = go * tanhapx(c);
                        }
                        uint32_t off = ((uint32_t)(b * 128 + u0t * 2)) ^ ((uint32_t)(b & 7) << 4);
                        *(__half2*)(BAc + H0T(p ^ 1) + off) =
                            __halves2half2(__float2half_rn(hv[0]), __float2half_rn(hv[1]));
                    }
                if (xduty) {
                    uint32_t off = ((uint32_t)(xb * 128 + xq * 2)) ^ ((uint32_t)(xb & 7) << 4);
                    *(__half*)(BAc + SXF(p ^ 1) + off) = __float2half_rn(xpre);
                }
            }
        } else {
            if (ts > 0) {
                float acc[2][4][4];
                #pragma unroll
                for (int mb = 0; mb < 2; mb++)
                    #pragma unroll
                    for (int G = 0; G < 4; G++)
                        #pragma unroll
                        for (int c = 0; c < 4; c++)
                            acc[mb][G][c] = bias[G][c & 1];

                // G1 = h1[ts-2]*Whh1^T + h0[ts-1]*Wih1^T (both in buffer p)
                gemm_t(acc, BAu + H1T(p), BAu + W1HF, aRow, bRow, hbA, xorA, hbB, xorB);
                gemm_t(acc, BAu + H0T(p), BAu + W1IF, aRow, bRow, hbA, xorA, hbB, xorB);

                #pragma unroll
                for (int mb = 0; mb < 2; mb++)
                    #pragma unroll
                    for (int rh = 0; rh < 2; rh++) {
                        const int b = mb * 16 + g4 + 8 * rh;
                        float hv[2];
                        #pragma unroll
                        for (int ui = 0; ui < 2; ui++) {
                            float gi = fsig   (acc[mb][0][rh * 2 + ui]);
                            float gf = fsig   (acc[mb][1][rh * 2 + ui]);
                            float gg = tanhapx(acc[mb][2][rh * 2 + ui]);
                            float go = fsig   (acc[mb][3][rh * 2 + ui]);
                            float &c = cs[mb][rh][ui];
                            c = gf * c + gi * gg;
                            hv[ui] = go * tanhapx(c);
                        }
                        if (ts < TT) {
                            uint32_t off = ((uint32_t)(b * 128 + u0t * 2)) ^ ((uint32_t)(b & 7) << 4);
                            *(__half2*)(BAc + H1T(p ^ 1) + off) =
                                __halves2half2(__float2half_rn(hv[0]), __float2half_rn(hv[1]));
                        } else {
                            *(float2*)((float*)(BAc + HS_OFF) + b * 64 + u0t) =
                                make_float2(hv[0], hv[1]);
                        }
                    }
            }
        }

        __syncthreads();   // single CTA barrier per iteration — deterministic
    }

    // ================= MLP head =================
    const float* hs = (const float*)(BAc + HS_OFF);
    float* W1s = (float*)(BAc + W1HF);
    for (int e = t; e < 64 * 64; e += THREADS) {
        int n = e >> 6, k = e & 63;
        W1s[k * 64 + n] = W1[e];
    }
    __syncthreads();

    float* sZ = (float*)(BAc + W0F);      // [28][64] fp32 in dead region
    for (int e = t; e < BT * 64; e += THREADS) {
        int b = e >> 6, n = e & 63;
        float sum = b1[n];
        #pragma unroll 8
        for (int k = 0; k < 64; k++)
            sum += W1s[k * 64 + n] * hs[b * 64 + k];
        sZ[b * 64 + n] = fmaxf(sum, 0.f);
    }
    __syncthreads();

    for (int e = t; e < BT * 12; e += THREADS) {
        int b = e / 12, o = e % 12;
        if (bBase + b < BATCH) {
            float sum = __ldg(&b2[o]);
            #pragma unroll 8
            for (int n = 0; n < 64; n++)
                sum += __ldg(&W2[o * 64 + n]) * sZ[b * 64 + n];
            out[(size_t)(bBase + b) * 12 + o] = sum;
        }
    }
}

extern "C" void kernel_launch(void* const* d_in, const int* in_sizes, int n_in,
                              void* d_out, int out_size)
{
    (void)in_sizes; (void)n_in; (void)out_size;
    cudaFuncSetAttribute(weather_lstm_ws,
                         cudaFuncAttributeMaxDynamicSharedMemorySize, SMEM_BYTES);
    weather_lstm_ws<<<NGRID, THREADS, SMEM_BYTES>>>(
        (const float*)d_in[0],
        (const float*)d_in[1],  (const float*)d_in[2],
        (const float*)d_in[3],  (const float*)d_in[4],
        (const float*)d_in[5],  (const float*)d_in[6],
        (const float*)d_in[7],  (const float*)d_in[8],
        (const float*)d_in[9],  (const float*)d_in[10],
        (const float*)d_in[11], (const float*)d_in[12],
        (float*)d_out);
}